// round 11
// baseline (speedup 1.0000x reference)
#include <cuda_runtime.h>
#include <cstdint>

#define NBLOCKS   444        // 148 SMs x 3 CTAs (64KB smem each), one wave
#define NTHREADS  256
#define STAGES    4
#define TILE_BYTES 8192
#define TILE_F4   (TILE_BYTES / 16)           // 512 float4 per tile per stream

#define SMEM_P    0
#define SMEM_T    (STAGES * TILE_BYTES)       // 32768
#define SMEM_BAR  (2 * STAGES * TILE_BYTES)   // 65536
#define SMEM_TOTAL (SMEM_BAR + STAGES * 8)    // 65568

__device__ float g_partials[NBLOCKS];
__device__ unsigned int g_done_count = 0;

__device__ __forceinline__ uint32_t smem_u32(const void* p) {
    uint32_t a;
    asm("{ .reg .u64 x; cvta.to.shared.u64 x, %1; cvt.u32.u64 %0, x; }"
        : "=r"(a) : "l"(p));
    return a;
}

__device__ __forceinline__ void mbar_wait(uint32_t mbar, uint32_t parity) {
    asm volatile(
        "{\n\t"
        ".reg .pred P;\n\t"
        "WAIT_%=:\n\t"
        "mbarrier.try_wait.parity.acquire.cta.shared::cta.b64 P, [%0], %1, 0x989680;\n\t"
        "@P bra.uni DONE_%=;\n\t"
        "bra.uni WAIT_%=;\n\t"
        "DONE_%=:\n\t"
        "}"
        :: "r"(mbar), "r"(parity) : "memory");
}

// Issue one pipeline stage: expect 2*TILE_BYTES, then two 8KB bulk copies
// (pred tile + targ tile) completing on the stage's mbarrier.
__device__ __forceinline__ void issue_tile(uint32_t smem_base,
                                           const float* __restrict__ p,
                                           const float* __restrict__ t,
                                           int s, long tile) {
    uint32_t mbar  = smem_base + SMEM_BAR + s * 8;
    uint32_t dst_p = smem_base + SMEM_P + s * TILE_BYTES;
    uint32_t dst_t = smem_base + SMEM_T + s * TILE_BYTES;
    const char* gp = (const char*)p + tile * (long)TILE_BYTES;
    const char* gt = (const char*)t + tile * (long)TILE_BYTES;
    asm volatile("mbarrier.arrive.expect_tx.shared.b64 _, [%0], %1;"
                 :: "r"(mbar), "r"(2 * TILE_BYTES) : "memory");
    asm volatile("cp.async.bulk.shared::cta.global.mbarrier::complete_tx::bytes "
                 "[%0], [%1], %2, [%3];"
                 :: "r"(dst_p), "l"(gp), "n"(TILE_BYTES), "r"(mbar) : "memory");
    asm volatile("cp.async.bulk.shared::cta.global.mbarrier::complete_tx::bytes "
                 "[%0], [%1], %2, [%3];"
                 :: "r"(dst_t), "l"(gt), "n"(TILE_BYTES), "r"(mbar) : "memory");
}

__global__ void __launch_bounds__(NTHREADS)
sse_tma_kernel(const float* __restrict__ p,
               const float* __restrict__ t,
               float* __restrict__ out,
               int n4, float scale) {
    extern __shared__ __align__(128) char smem[];
    const uint32_t smem_base = smem_u32(smem);
    const int tid = threadIdx.x;

    const int ntiles = n4 / TILE_F4;
    // Tiles for this CTA: blockIdx.x + k*gridDim.x, k = 0..nt-1
    int nt = 0;
    if ((int)blockIdx.x < ntiles)
        nt = (ntiles - 1 - (int)blockIdx.x) / (int)gridDim.x + 1;

    if (tid == 0) {
        #pragma unroll
        for (int s = 0; s < STAGES; s++)
            asm volatile("mbarrier.init.shared.b64 [%0], %1;"
                         :: "r"(smem_base + SMEM_BAR + s * 8), "r"(1) : "memory");
    }
    __syncthreads();
    asm volatile("fence.proxy.async.shared::cta;" ::: "memory");

    // Prologue: fill the pipeline
    if (tid == 0) {
        int pre = nt < STAGES ? nt : STAGES;
        for (int s = 0; s < pre; s++)
            issue_tile(smem_base, p, t, s,
                       (long)blockIdx.x + (long)s * gridDim.x);
    }

    float acc0 = 0.0f, acc1 = 0.0f;

    for (int k = 0; k < nt; k++) {
        const int s = k & (STAGES - 1);
        const uint32_t par = (uint32_t)((k >> 2) & 1);   // STAGES = 4
        mbar_wait(smem_base + SMEM_BAR + s * 8, par);

        const float4* sp = (const float4*)(smem + SMEM_P + s * TILE_BYTES);
        const float4* st = (const float4*)(smem + SMEM_T + s * TILE_BYTES);
        float4 a0 = sp[tid];
        float4 a1 = sp[tid + NTHREADS];
        float4 b0 = st[tid];
        float4 b1 = st[tid + NTHREADS];

        float d;
        d = a0.x - b0.x; acc0 = fmaf(d, d, acc0);
        d = a0.y - b0.y; acc0 = fmaf(d, d, acc0);
        d = a0.z - b0.z; acc0 = fmaf(d, d, acc0);
        d = a0.w - b0.w; acc0 = fmaf(d, d, acc0);
        d = a1.x - b1.x; acc1 = fmaf(d, d, acc1);
        d = a1.y - b1.y; acc1 = fmaf(d, d, acc1);
        d = a1.z - b1.z; acc1 = fmaf(d, d, acc1);
        d = a1.w - b1.w; acc1 = fmaf(d, d, acc1);

        __syncthreads();   // all lanes done reading stage s
        if (tid == 0) {
            int nk = k + STAGES;
            if (nk < nt)
                issue_tile(smem_base, p, t, s,
                           (long)blockIdx.x + (long)nk * gridDim.x);
        }
    }

    // Tail: elements beyond ntiles*TILE_F4 (0 for this shape, insurance only)
    if (blockIdx.x == 0) {
        const float4* pf = (const float4*)p;
        const float4* tf = (const float4*)t;
        for (int i = ntiles * TILE_F4 + tid; i < n4; i += NTHREADS) {
            float4 a = pf[i], b = tf[i];
            float d;
            d = a.x - b.x; acc0 = fmaf(d, d, acc0);
            d = a.y - b.y; acc0 = fmaf(d, d, acc0);
            d = a.z - b.z; acc0 = fmaf(d, d, acc0);
            d = a.w - b.w; acc0 = fmaf(d, d, acc0);
        }
    }

    float acc = acc0 + acc1;

    // Warp reduction
    #pragma unroll
    for (int off = 16; off > 0; off >>= 1)
        acc += __shfl_down_sync(0xFFFFFFFFu, acc, off);

    __shared__ float warp_sums[NTHREADS / 32];
    const int lane = tid & 31;
    const int wid  = tid >> 5;
    if (lane == 0) warp_sums[wid] = acc;
    __syncthreads();

    __shared__ bool is_last;
    if (wid == 0) {
        float v = (lane < (NTHREADS / 32)) ? warp_sums[lane] : 0.0f;
        #pragma unroll
        for (int off = 4; off > 0; off >>= 1)
            v += __shfl_down_sync(0xFFFFFFFFu, v, off);
        if (lane == 0) {
            g_partials[blockIdx.x] = v;
            __threadfence();
            unsigned int prev = atomicAdd(&g_done_count, 1u);
            is_last = (prev == (unsigned int)(gridDim.x - 1));
        }
    }
    __syncthreads();

    if (is_last) {
        float v = 0.0f;
        for (int b = tid; b < (int)gridDim.x; b += NTHREADS)
            v += g_partials[b];
        #pragma unroll
        for (int off = 16; off > 0; off >>= 1)
            v += __shfl_down_sync(0xFFFFFFFFu, v, off);
        if (lane == 0) warp_sums[wid] = v;
        __syncthreads();
        if (wid == 0) {
            float s = (lane < (NTHREADS / 32)) ? warp_sums[lane] : 0.0f;
            #pragma unroll
            for (int off = 4; off > 0; off >>= 1)
                s += __shfl_down_sync(0xFFFFFFFFu, s, off);
            if (lane == 0) {
                out[0] = s * scale;
                g_done_count = 0;   // reset for next graph replay
            }
        }
    }
}

extern "C" void kernel_launch(void* const* d_in, const int* in_sizes, int n_in,
                              void* d_out, int out_size) {
    const float* pred = (const float*)d_in[0];
    const float* targ = (const float*)d_in[1];
    float* out = (float*)d_out;

    int n = in_sizes[0];       // B * S * 2 = 16,769,024
    int n4 = n / 4;
    float scale = 2.0f / (float)n;

    cudaFuncSetAttribute(sse_tma_kernel,
                         cudaFuncAttributeMaxDynamicSharedMemorySize,
                         SMEM_TOTAL);

    sse_tma_kernel<<<NBLOCKS, NTHREADS, SMEM_TOTAL>>>(pred, targ, out,
                                                      n4, scale);
}

// round 12
// speedup vs baseline: 1.0083x; 1.0083x over previous
#include <cuda_runtime.h>

#define NBLOCKS 592
#define NTHREADS 256

__device__ float g_partials[NBLOCKS];
__device__ unsigned int g_done_count = 0;

__device__ __forceinline__ float4 ldcs4(const float4* p) {
    return __ldcs(p);
}

// Single-kernel SSE reduction: grid-stride unroll x4 with front-batched
// loads (R4's proven-best memory shape), block partials to a device
// global, last-block-done finish (R5's proven-cheap wall structure).
// __launch_bounds__(256, 6) caps regs at 42: enough for the 8-load batch
// (32 data regs + addressing, proven schedulable in 32 by R4) without
// letting ptxas balloon to 52 (R8) or strangling it to 32 with epilogue
// live-state (R9).
__global__ void __launch_bounds__(NTHREADS, 6)
sse_reduce_kernel(const float4* __restrict__ p,
                  const float4* __restrict__ t,
                  float* __restrict__ out,
                  int n4, float scale) {
    const int idx    = blockIdx.x * blockDim.x + threadIdx.x;
    const int stride = gridDim.x * blockDim.x;

    float acc0 = 0.0f, acc1 = 0.0f, acc2 = 0.0f, acc3 = 0.0f;

    int i = idx;
    for (; i + 3 * stride < n4; i += 4 * stride) {
        float4 a0 = ldcs4(&p[i]);
        float4 a1 = ldcs4(&p[i +     stride]);
        float4 a2 = ldcs4(&p[i + 2 * stride]);
        float4 a3 = ldcs4(&p[i + 3 * stride]);
        float4 b0 = ldcs4(&t[i]);
        float4 b1 = ldcs4(&t[i +     stride]);
        float4 b2 = ldcs4(&t[i + 2 * stride]);
        float4 b3 = ldcs4(&t[i + 3 * stride]);

        float d;
        d = a0.x - b0.x; acc0 = fmaf(d, d, acc0);
        d = a0.y - b0.y; acc0 = fmaf(d, d, acc0);
        d = a0.z - b0.z; acc0 = fmaf(d, d, acc0);
        d = a0.w - b0.w; acc0 = fmaf(d, d, acc0);
        d = a1.x - b1.x; acc1 = fmaf(d, d, acc1);
        d = a1.y - b1.y; acc1 = fmaf(d, d, acc1);
        d = a1.z - b1.z; acc1 = fmaf(d, d, acc1);
        d = a1.w - b1.w; acc1 = fmaf(d, d, acc1);
        d = a2.x - b2.x; acc2 = fmaf(d, d, acc2);
        d = a2.y - b2.y; acc2 = fmaf(d, d, acc2);
        d = a2.z - b2.z; acc2 = fmaf(d, d, acc2);
        d = a2.w - b2.w; acc2 = fmaf(d, d, acc2);
        d = a3.x - b3.x; acc3 = fmaf(d, d, acc3);
        d = a3.y - b3.y; acc3 = fmaf(d, d, acc3);
        d = a3.z - b3.z; acc3 = fmaf(d, d, acc3);
        d = a3.w - b3.w; acc3 = fmaf(d, d, acc3);
    }
    for (; i < n4; i += stride) {
        float4 a = ldcs4(&p[i]);
        float4 b = ldcs4(&t[i]);
        float d;
        d = a.x - b.x; acc0 = fmaf(d, d, acc0);
        d = a.y - b.y; acc0 = fmaf(d, d, acc0);
        d = a.z - b.z; acc0 = fmaf(d, d, acc0);
        d = a.w - b.w; acc0 = fmaf(d, d, acc0);
    }

    float acc = (acc0 + acc1) + (acc2 + acc3);

    // Warp reduction
    #pragma unroll
    for (int off = 16; off > 0; off >>= 1)
        acc += __shfl_down_sync(0xFFFFFFFFu, acc, off);

    __shared__ float warp_sums[NTHREADS / 32];
    const int lane = threadIdx.x & 31;
    const int wid  = threadIdx.x >> 5;
    if (lane == 0) warp_sums[wid] = acc;
    __syncthreads();

    __shared__ bool is_last;
    if (wid == 0) {
        float v = (lane < (NTHREADS / 32)) ? warp_sums[lane] : 0.0f;
        #pragma unroll
        for (int off = 4; off > 0; off >>= 1)
            v += __shfl_down_sync(0xFFFFFFFFu, v, off);
        if (lane == 0) {
            g_partials[blockIdx.x] = v;
            __threadfence();
            unsigned int prev = atomicAdd(&g_done_count, 1u);
            is_last = (prev == (unsigned int)(gridDim.x - 1));
        }
    }
    __syncthreads();

    // Last block to finish reduces all partials and writes the result.
    if (is_last) {
        float v = 0.0f;
        for (int b = threadIdx.x; b < (int)gridDim.x; b += NTHREADS)
            v += g_partials[b];
        #pragma unroll
        for (int off = 16; off > 0; off >>= 1)
            v += __shfl_down_sync(0xFFFFFFFFu, v, off);
        if (lane == 0) warp_sums[wid] = v;
        __syncthreads();
        if (wid == 0) {
            float s = (lane < (NTHREADS / 32)) ? warp_sums[lane] : 0.0f;
            #pragma unroll
            for (int off = 4; off > 0; off >>= 1)
                s += __shfl_down_sync(0xFFFFFFFFu, s, off);
            if (lane == 0) {
                out[0] = s * scale;
                g_done_count = 0;   // reset for next graph replay
            }
        }
    }
}

extern "C" void kernel_launch(void* const* d_in, const int* in_sizes, int n_in,
                              void* d_out, int out_size) {
    const float* pred = (const float*)d_in[0];
    const float* targ = (const float*)d_in[1];
    float* out = (float*)d_out;

    int n = in_sizes[0];       // B * S * 2 = 16,769,024 (divisible by 4)
    int n4 = n / 4;
    float scale = 2.0f / (float)n;

    sse_reduce_kernel<<<NBLOCKS, NTHREADS>>>((const float4*)pred,
                                             (const float4*)targ,
                                             out, n4, scale);
}